// round 3
// baseline (speedup 1.0000x reference)
#include <cuda_runtime.h>

// STDP with TE=1.0 collapses: e[i][j] = x_T[i]*q_T[j] - p_T[i]*y_T[j].
// x,y are EMA traces (v += (s - v)/2); geometric decay means only the last
// K steps matter. K_y=20 (err ~1e-6, 300x under tolerance), K_x=32 (exact
// to fp32). Single fused kernel, y/q kept in registers (no smem round-trip),
// final Horner load doubles as q_last.

#define N 1024
#define KY 20
#define KX 32
#define ROWS 8
#define THREADS 256

__global__ __launch_bounds__(THREADS, 1)
void stdp_fused_kernel(const float* __restrict__ pre,
                       const float* __restrict__ post,
                       float* __restrict__ e,
                       int T) {
    __shared__ float sx[ROWS];  // x traces for this block's rows
    __shared__ float sp[ROWS];  // pre last-row values for this block's rows

    const int tid = threadIdx.x;
    const int i0 = blockIdx.x * ROWS;

    // ---- Phase 1a: y trace + q_last for this thread's 4 columns (regs) ----
    const float4* postv = reinterpret_cast<const float4*>(post);
    const int j4 = tid;                     // float4 column index 0..255
    const int ty0 = T - KY;
    float4 y = make_float4(0.f, 0.f, 0.f, 0.f);
    float4 q;                               // last loaded q = q at t = T-1
    #pragma unroll
    for (int t = 0; t < KY; t++) {
        q = postv[(size_t)(ty0 + t) * (N / 4) + j4];
        // reference rounding order: y = y + (q - y) * 0.5
        y.x = y.x + (q.x - y.x) * 0.5f;
        y.y = y.y + (q.y - y.y) * 0.5f;
        y.z = y.z + (q.z - y.z) * 0.5f;
        y.w = y.w + (q.w - y.w) * 0.5f;
    }

    // ---- Phase 1b: x traces, one warp per row (dyadic weighted reduce) ----
    const int w = tid >> 5;
    const int lane = tid & 31;
    {
        const int i = i0 + w;
        float p = pre[(size_t)(T - KX + lane) * N + i];
        // weight 0.5^(KX - lane): exact power of two (p in {0,1})
        float wt = __int_as_float((127 - (KX - lane)) << 23);
        float v = p * wt;
        #pragma unroll
        for (int off = 16; off; off >>= 1)
            v += __shfl_xor_sync(0xffffffffu, v, off);
        if (lane == 0)       sx[w] = v;
        if (lane == KX - 1)  sp[w] = p;   // p at t = T-1
    }
    __syncthreads();

    // ---- Phase 2: e[i][j] = x[i]*q[j] - p[i]*y[j], float4 stores ----
    float4* ev = reinterpret_cast<float4*>(e);
    #pragma unroll
    for (int r = 0; r < ROWS; r++) {
        const float xi = sx[r];
        const float pi = sp[r];
        float4 o;
        o.x = xi * q.x - pi * y.x;
        o.y = xi * q.y - pi * y.y;
        o.z = xi * q.z - pi * y.z;
        o.w = xi * q.w - pi * y.w;
        ev[(size_t)(i0 + r) * (N / 4) + j4] = o;
    }
}

extern "C" void kernel_launch(void* const* d_in, const int* in_sizes, int n_in,
                              void* d_out, int out_size) {
    const float* pre  = (const float*)d_in[0];   // [T, 1024]
    const float* post = (const float*)d_in[1];   // [T, 1024]
    float* e = (float*)d_out;                    // [1024, 1024]
    int T = in_sizes[0] / N;                     // 256

    stdp_fused_kernel<<<N / ROWS, THREADS>>>(pre, post, e, T);
}

// round 4
// speedup vs baseline: 1.0047x; 1.0047x over previous
#include <cuda_runtime.h>

// STDP with TE=1.0 collapses: e[i][j] = x_T[i]*q_T[j] - p_T[i]*y_T[j].
// x,y are EMA traces (v += (s - v)/2); only the last K steps matter
// (0.5^K below fp32 noise / tolerance). KY=20, KX=32.
//
// 2D-tiled single kernel: 256 CTAs (16 row-tiles x 16 col-tiles), each
// producing a 64x64 output tile. Tail tiles of pre/post are staged into
// smem with fully coalesced loads (one MLP burst), Horner recurrences run
// from smem (reference rounding order), then a register-resident rank-2
// outer product with float4 stores.

#define N   1024
#define KY  20
#define KX  32
#define BR  64
#define BC  64
#define THREADS 256

__global__ __launch_bounds__(THREADS)
void stdp_fused_kernel(const float* __restrict__ pre,
                       const float* __restrict__ post,
                       float* __restrict__ e,
                       int T) {
    __shared__ __align__(16) float s_q[KY * BC];   // post tail tile
    __shared__ __align__(16) float s_p[KX * BR];   // pre tail tile
    __shared__ __align__(16) float sy[BC];         // y traces
    __shared__ __align__(16) float sql[BC];        // q at t = T-1
    __shared__ float sx[BR];                       // x traces
    __shared__ float spl[BR];                      // p at t = T-1

    const int tid = threadIdx.x;
    const int r0 = (blockIdx.x >> 4) * BR;         // row-tile origin
    const int c0 = (blockIdx.x & 15) * BC;         // col-tile origin

    // ---- Stage tails into smem (coalesced; 13 KB total, one burst) ----
    #pragma unroll
    for (int k = 0; k < (KY * BC) / THREADS; k++) {    // 5 iters
        int idx = tid + k * THREADS;
        int t = idx >> 6, c = idx & 63;
        s_q[idx] = post[(size_t)(T - KY + t) * N + c0 + c];
    }
    #pragma unroll
    for (int k = 0; k < (KX * BR) / THREADS; k++) {    // 8 iters
        int idx = tid + k * THREADS;
        int t = idx >> 6, r = idx & 63;
        s_p[idx] = pre[(size_t)(T - KX + t) * N + r0 + r];
    }
    __syncthreads();

    // ---- Horner recurrences from smem (reference rounding order) ----
    if (tid < BC) {
        float y = 0.0f;
        #pragma unroll
        for (int t = 0; t < KY; t++) {
            float q = s_q[t * BC + tid];
            y = y + (q - y) * 0.5f;
        }
        sy[tid]  = y;
        sql[tid] = s_q[(KY - 1) * BC + tid];
    } else if (tid < BC + BR) {
        int r = tid - BC;
        float x = 0.0f;
        #pragma unroll
        for (int t = 0; t < KX; t++) {
            float p = s_p[t * BR + r];
            x = x + (p - x) * 0.5f;
        }
        sx[r]  = x;
        spl[r] = s_p[(KX - 1) * BR + r];
    }
    __syncthreads();

    // ---- e[i][j] = x[i]*q[j] - p[i]*y[j], float4 stores ----
    const int c4 = tid & 15;                       // this thread's float4 col
    const float4 q = reinterpret_cast<const float4*>(sql)[c4];
    const float4 y = reinterpret_cast<const float4*>(sy)[c4];
    float4* ev = reinterpret_cast<float4*>(e);
    const int rbase = tid >> 4;                    // 0..15
    #pragma unroll
    for (int it = 0; it < 4; it++) {
        int r = rbase + 16 * it;
        float xi = sx[r];
        float pi = spl[r];
        float4 o;
        o.x = xi * q.x - pi * y.x;
        o.y = xi * q.y - pi * y.y;
        o.z = xi * q.z - pi * y.z;
        o.w = xi * q.w - pi * y.w;
        ev[(size_t)(r0 + r) * (N / 4) + (c0 >> 2) + c4] = o;
    }
}

extern "C" void kernel_launch(void* const* d_in, const int* in_sizes, int n_in,
                              void* d_out, int out_size) {
    const float* pre  = (const float*)d_in[0];   // [T, 1024]
    const float* post = (const float*)d_in[1];   // [T, 1024]
    float* e = (float*)d_out;                    // [1024, 1024]
    int T = in_sizes[0] / N;                     // 256

    stdp_fused_kernel<<<(N / BR) * (N / BC), THREADS>>>(pre, post, e, T);
}